// round 17
// baseline (speedup 1.0000x reference)
#include <cuda_runtime.h>
#include <cuda_fp16.h>
#include <cuda_bf16.h>

#define Bz 256
#define Sz 512
#define Ez 100
#define Hz 64
#define Gz 256      // 4*H
#define Vz 50000
#define VP 50048    // padded vocab rows (391*128)
#define NC 512      // 2 dirs * 256 entries
#define KPH 112     // padded K in halfs

// Table layout: [v][dir][cell e][gate i,f,g,o]  (gate-interleaved), fp16
__device__ __half g_tableh[(size_t)VP * NC];      // 51.2 MB (L2-resident)
__device__ __half g_embh[(size_t)VP * KPH];       // padded fp16 embeddings
__device__ __half g_wihh[2 * 256 * KPH];          // permuted fp16 W_ih
__device__ float  g_hfin[2 * Bz * Hz];

// f32-accumulator MMA (accumulate onto D)
#define MMA16816(c0,c1,c2,c3, a0,a1,a2,a3, b0,b1) \
    asm("mma.sync.aligned.m16n8k16.row.col.f32.f16.f16.f32 " \
        "{%0,%1,%2,%3}, {%4,%5,%6,%7}, {%8,%9}, {%0,%1,%2,%3};" \
        : "+f"(c0), "+f"(c1), "+f"(c2), "+f"(c3) \
        : "r"(a0), "r"(a1), "r"(a2), "r"(a3), "r"(b0), "r"(b1))

// packed sigmoid: sigm(x) = 0.5*tanh(0.5x) + 0.5  (f16x2)
#define SIGM2(dst, src, h05) \
    asm("{ .reg .b32 tmp;\n\t" \
        "mul.f16x2 tmp, %1, %2;\n\t" \
        "tanh.approx.f16x2 tmp, tmp;\n\t" \
        "fma.rn.f16x2 %0, tmp, %2, %2; }" \
        : "=r"(dst) : "r"(src), "r"(h05))

#define PRMT(d, a, b, sel) \
    asm("prmt.b32 %0, %1, %2, %3;" : "=r"(d) : "r"(a), "r"(b), "n"(sel))

__device__ __forceinline__ unsigned int tanh2_ap(unsigned int x) {
    unsigned int y;
    asm("tanh.approx.f16x2 %0, %1;" : "=r"(y) : "r"(x));
    return y;
}
__device__ __forceinline__ unsigned int hadd2u(unsigned int a, unsigned int b) {
    unsigned int d;
    asm("add.rn.f16x2 %0, %1, %2;" : "=r"(d) : "r"(a), "r"(b));
    return d;
}
__device__ __forceinline__ unsigned int hmul2u(unsigned int a, unsigned int b) {
    unsigned int d;
    asm("mul.f16x2 %0, %1, %2;" : "=r"(d) : "r"(a), "r"(b));
    return d;
}
__device__ __forceinline__ unsigned int hfma2u(unsigned int a, unsigned int b,
                                               unsigned int c) {
    unsigned int d;
    asm("fma.rn.f16x2 %0, %1, %2, %3;" : "=r"(d) : "r"(a), "r"(b), "r"(c));
    return d;
}
__device__ __forceinline__ unsigned int pkf(float a, float b) {
    __half2 h = __floats2half2_rn(a, b);
    return *(unsigned int*)&h;
}

#define H05C 0x38003800u   // half2(0.5, 0.5)

// packed LSTM cell update: returns h (f16x2), updates cst (f16x2)
__device__ __forceinline__ unsigned int lstm_update(unsigned int ui, unsigned int uf,
                                                    unsigned int ug, unsigned int uo,
                                                    unsigned int& cst) {
    unsigned int si, sf, so;
    SIGM2(si, ui, H05C);
    SIGM2(sf, uf, H05C);
    SIGM2(so, uo, H05C);
    unsigned int tgg = tanh2_ap(ug);
    cst = hfma2u(sf, cst, hmul2u(si, tgg));
    return hmul2u(so, tanh2_ap(cst));
}

// ---------------------------------------------------------------------------
// Kernel 0a: convert embeddings -> fp16 padded [VP][112]
// ---------------------------------------------------------------------------
__global__ __launch_bounds__(256)
void cvt_emb(const float* __restrict__ emb)
{
    int row = blockIdx.x * 4 + (threadIdx.x >> 6);
    int q   = threadIdx.x & 63;            // half2 index within row
    if (q >= KPH / 2) return;
    __half2 v = __half2half2(__float2half(0.0f));
    if (row < Vz && q < 50) {
        float2 f = ((const float2*)emb)[(size_t)row * 50 + q];
        v = __floats2half2_rn(f.x, f.y);
    }
    ((__half2*)g_embh)[(size_t)row * (KPH / 2) + q] = v;
}

// ---------------------------------------------------------------------------
// Kernel 0b: convert W_ih -> fp16, gate-permuted rows: g_wihh[dir][cnew][112]
//            where cnew = 4*e + gate holds W_ih row gate*64 + e.
// ---------------------------------------------------------------------------
__global__ __launch_bounds__(64)
void cvt_wih(const float* __restrict__ Wf, const float* __restrict__ Wb)
{
    int dir  = blockIdx.x >> 8;
    int cnew = blockIdx.x & 255;
    int wrow = (cnew & 3) * 64 + (cnew >> 2);
    const float2* W2 = (const float2*)(dir ? Wb : Wf) + (size_t)wrow * 50;
    int q = threadIdx.x;
    if (q >= KPH / 2) return;
    __half2 v = (q < 50) ? __floats2half2_rn(W2[q].x, W2[q].y)
                         : __half2half2(__float2half(0.0f));
    ((__half2*)g_wihh)[((size_t)dir * 256 + cnew) * (KPH / 2) + q] = v;
}

// ---------------------------------------------------------------------------
// Kernel 1: vocab-table GEMM via HMMA (fp16 operands pre-converted).
// Staging = pure uint4 copies with shift-only indexing. Unchanged from R13.
// ---------------------------------------------------------------------------
#define LDH 120    // smem row stride in halfs

__global__ __launch_bounds__(256)
void vocab_gemm(const float* __restrict__ bih_f,
                const float* __restrict__ bhh_f,
                const float* __restrict__ bih_b,
                const float* __restrict__ bhh_b)
{
    const int tid  = threadIdx.x;
    const int lane = tid & 31;
    const int w    = tid >> 5;
    const int gid  = lane >> 2;
    const int tg   = lane & 3;
    const int wm   = w & 3;
    const int wn   = w >> 2;

    const int rb = blockIdx.x * 128;
    const int cb = blockIdx.y * 64;
    const int dir = cb >> 8;
    const int gb  = cb & 255;          // column base within dir

    const float* __restrict__ bi = dir ? bih_b : bih_f;
    const float* __restrict__ bh = dir ? bhh_b : bhh_f;

    __shared__ __align__(16) __half As[128 * LDH];
    __shared__ __align__(16) __half Bs[64 * LDH];
    __shared__ float bias_s[64];

    if (tid < 64) {
        int cloc = gb + tid;
        int wrow = (cloc & 3) * 64 + (cloc >> 2);   // gate*64 + e
        bias_s[tid] = bi[wrow] + bh[wrow];
    }

    // Stage A: 128 rows x 14 uint4; 2 threads per row, 7 uint4 each
    {
        int m = tid >> 1, h = tid & 1;
        const uint4* src = (const uint4*)(g_embh + (size_t)(rb + m) * KPH) + h * 7;
        uint4* dst = (uint4*)(As + m * LDH) + h * 7;
#pragma unroll
        for (int i = 0; i < 7; i++) dst[i] = src[i];
    }
    // Stage B: 64 rows x 14 uint4; 4 threads per row
    {
        int m = tid >> 2, q0 = tid & 3;
        const uint4* src = (const uint4*)(g_wihh + ((size_t)dir * 256 + gb + m) * KPH);
        uint4* dst = (uint4*)(Bs + m * LDH);
#pragma unroll
        for (int i = 0; i < 4; i++) {
            int q = q0 + 4 * i;
            if (q < 14) dst[q] = src[q];
        }
    }
    __syncthreads();

    float acc[2][4][4];
#pragma unroll
    for (int mt = 0; mt < 2; mt++)
#pragma unroll
        for (int nt = 0; nt < 4; nt++)
#pragma unroll
            for (int i = 0; i < 4; i++) acc[mt][nt][i] = 0.0f;

#pragma unroll
    for (int kt = 0; kt < 7; kt++) {
        unsigned int a[2][4], b[4][2];
#pragma unroll
        for (int mt = 0; mt < 2; mt++) {
            int r = wm * 32 + mt * 16 + gid;
            const unsigned int* p0 = (const unsigned int*)(As + r * LDH + kt * 16 + 2 * tg);
            const unsigned int* p1 = (const unsigned int*)(As + (r + 8) * LDH + kt * 16 + 2 * tg);
            a[mt][0] = p0[0];
            a[mt][1] = p1[0];
            a[mt][2] = p0[4];
            a[mt][3] = p1[4];
        }
#pragma unroll
        for (int nt = 0; nt < 4; nt++) {
            int n = wn * 32 + nt * 8 + gid;
            const unsigned int* p = (const unsigned int*)(Bs + n * LDH + kt * 16 + 2 * tg);
            b[nt][0] = p[0];
            b[nt][1] = p[4];
        }
#pragma unroll
        for (int mt = 0; mt < 2; mt++)
#pragma unroll
            for (int nt = 0; nt < 4; nt++)
                MMA16816(acc[mt][nt][0], acc[mt][nt][1], acc[mt][nt][2], acc[mt][nt][3],
                         a[mt][0], a[mt][1], a[mt][2], a[mt][3],
                         b[nt][0], b[nt][1]);
    }

#pragma unroll
    for (int mt = 0; mt < 2; mt++) {
#pragma unroll
        for (int nt = 0; nt < 4; nt++) {
            int n = wn * 32 + nt * 8 + 2 * tg;
            float b0 = bias_s[n], b1 = bias_s[n + 1];
            int r0 = rb + wm * 32 + mt * 16 + gid;
            int r1 = r0 + 8;
            *(__half2*)&g_tableh[(size_t)r0 * NC + cb + n] =
                __floats2half2_rn(acc[mt][nt][0] + b0, acc[mt][nt][1] + b1);
            *(__half2*)&g_tableh[(size_t)r1 * NC + cb + n] =
                __floats2half2_rn(acc[mt][nt][2] + b0, acc[mt][nt][3] + b1);
        }
    }
}

// ---------------------------------------------------------------------------
// Kernel 2: LSTM recurrence — DUAL warp-group design.
// One block = 2 independent 128-thread groups (group g = direction g), same
// 4 batch rows, synchronized by NAMED barriers (bar.sync g+1, 128) so the
// two recurrences drift and hide each other's per-step latency on the SMSPs.
// Per group: 4 warps; warp wg owns cells [16wg,16wg+16) as 2 cell-halves;
// 4 m-tiles x 4 k-steps = 16 MMAs/warp/step, depth-2 chains (R13 internals):
// permuted-gate A packing, 3-phase clamped prefetch ring, PRMT f16 xp merge,
// packed f16x2 update. Grid 64 blocks (Bz/4), 8 chains per SM.
// ---------------------------------------------------------------------------
#define HP 72    // h smem row stride (halfs)

__global__ __launch_bounds__(256)
void lstm_rec(const int* __restrict__ x,
              const float* __restrict__ Whh_f,
              const float* __restrict__ Whh_b)
{
    const int tid  = threadIdx.x;
    const int lane = tid & 31;
    const int dir  = tid >> 7;          // warp-group = direction
    const int gw   = (tid >> 5) & 3;    // warp within group (0..3)
    const int gid  = lane >> 2;
    const int tg   = lane & 3;
    const int e0   = gw * 16 + gid;     // owned cell, half 0
    const int e1   = e0 + 8;            // owned cell, half 1
    const int n0   = 2 * tg;            // chains n0, n0+1 (real if tg<2)
    const bool real = (tg < 2);

    const int bg  = blockIdx.x;
    const float* __restrict__ W = dir ? Whh_b : Whh_f;
    // per-thread table base for each cell (bytes): dir*512 + 8*e
    const char* __restrict__ tb0 = (const char*)g_tableh + dir * 512 + 8 * e0;
    const char* __restrict__ tb1 = (const char*)g_tableh + dir * 512 + 8 * e1;

    __shared__ int toks[4][Sz];                          // byte offsets
    __shared__ __align__(16) __half h_sh[2][2][8 * HP];  // [group][pb][...]

    for (int p = tid; p < 4 * Sz; p += 256) {
        int r = p >> 9, t_ = p & 511;
        toks[r][t_] = x[(bg * 4 + r) * Sz + t_] << 10;   // tok * NC * 2
    }
    for (int p = tid; p < 2 * 2 * 8 * HP; p += 256)
        ((__half*)h_sh)[p] = __ushort_as_half((unsigned short)0);

    // A fragments, permuted-gate packing, fp16.
    // m-tile m: cell e_{m>>1}; rows gid -> gate (2*(m&1)), gid+8 -> gate (2*(m&1)+1)
    unsigned int afr[4][4][4];
#pragma unroll
    for (int m = 0; m < 4; m++) {
        const int ec = (m >> 1) ? e1 : e0;
        const float* r0 = W + (size_t)((2 * (m & 1))     * 64 + ec) * Hz;
        const float* r1 = W + (size_t)((2 * (m & 1) + 1) * 64 + ec) * Hz;
#pragma unroll
        for (int kt = 0; kt < 4; kt++) {
            int cb_ = kt * 16 + tg * 2;
            __half2 a0 = __floats2half2_rn(r0[cb_],     r0[cb_ + 1]);
            __half2 a1 = __floats2half2_rn(r1[cb_],     r1[cb_ + 1]);
            __half2 a2 = __floats2half2_rn(r0[cb_ + 8], r0[cb_ + 9]);
            __half2 a3 = __floats2half2_rn(r1[cb_ + 8], r1[cb_ + 9]);
            afr[m][kt][0] = *(unsigned int*)&a0;
            afr[m][kt][1] = *(unsigned int*)&a1;
            afr[m][kt][2] = *(unsigned int*)&a2;
            afr[m][kt][3] = *(unsigned int*)&a3;
        }
    }

    unsigned int cst0 = 0u, cst1 = 0u;   // packed f16x2 cell states
    unsigned int hn0  = 0u, hn1  = 0u;

    __syncthreads();   // staging complete; groups now drift independently

    int t = dir ? (Sz - 1) : 0;
    const int dt = dir ? -1 : 1;
    int pb = 0;

    // 3-phase xp ring: xr[ph][cellhalf][chain] (uint2 = {(i,f),(g,o)} fp16)
    uint2 xr[3][2][2];
#pragma unroll
    for (int p = 0; p < 3; p++)
#pragma unroll
        for (int h = 0; h < 2; h++) {
            xr[p][h][0] = make_uint2(0u, 0u);
            xr[p][h][1] = make_uint2(0u, 0u);
        }
    if (real) {
        int o0 = toks[n0][t], o1 = toks[n0 + 1][t];
        xr[0][0][0] = *(const uint2*)(tb0 + o0);
        xr[0][0][1] = *(const uint2*)(tb0 + o1);
        xr[0][1][0] = *(const uint2*)(tb1 + o0);
        xr[0][1][1] = *(const uint2*)(tb1 + o1);
        int t1 = t + dt;
        o0 = toks[n0][t1]; o1 = toks[n0 + 1][t1];
        xr[1][0][0] = *(const uint2*)(tb0 + o0);
        xr[1][0][1] = *(const uint2*)(tb0 + o1);
        xr[1][1][0] = *(const uint2*)(tb1 + o0);
        xr[1][1][1] = *(const uint2*)(tb1 + o1);
    }

    __half* const hbase = (__half*)h_sh[dir];
    const unsigned barid = dir + 1;

#define GBAR() asm volatile("bar.sync %0, %1;" :: "r"(barid), "n"(128) : "memory")

#define LSTM_STEP(PH) do {                                                     \
    const __half* hrd = hbase + pb * (8 * HP);                                 \
    unsigned int b0[4], b1[4];                                                 \
    _Pragma("unroll")                                                          \
    for (int kt = 0; kt < 4; kt++) {                                           \
        const unsigned int* hw =                                               \
            (const unsigned int*)(hrd + gid * HP + kt * 16 + tg * 2);          \
        b0[kt] = hw[0];                                                        \
        b1[kt] = hw[4];                                                        \
    }                                                                          \
    float pm[4][4], qm[4][4];                                                  \
    _Pragma("unroll")                                                          \
    for (int m = 0; m < 4; m++)                                                \
        _Pragma("unroll")                                                      \
        for (int i = 0; i < 4; i++) { pm[m][i] = 0.0f; qm[m][i] = 0.0f; }      \
    _Pragma("unroll")                                                          \
    for (int m = 0; m < 4; m++) {                                              \
        MMA16816(pm[m][0], pm[m][1], pm[m][2], pm[m][3],                       \
                 afr[m][0][0], afr[m][0][1], afr[m][0][2], afr[m][0][3],       \
                 b0[0], b1[0]);                                                \
        MMA16816(qm[m][0], qm[m][1], qm[m][2], qm[m][3],                       \
                 afr[m][2][0], afr[m][2][1], afr[m][2][2], afr[m][2][3],       \
                 b0[2], b1[2]);                                                \
    }                                                                          \
    {   /* prefetch xp for step s+2 (clamped) in the MMA shadow */             \
        const int PH2 = (PH + 2) % 3;                                          \
        if (real) {                                                            \
            int t2 = t + 2 * dt;                                               \
            t2 = t2 < 0 ? 0 : (t2 > Sz - 1 ? Sz - 1 : t2);                     \
            int oo0 = toks[n0][t2], oo1 = toks[n0 + 1][t2];                    \
            xr[PH2][0][0] = *(const uint2*)(tb0 + oo0);                        \
            xr[PH2][0][1] = *(const uint2*)(tb0 + oo1);                        \
            xr[PH2][1][0] = *(const uint2*)(tb1 + oo0);                        \
            xr[PH2][1][1] = *(const uint2*)(tb1 + oo1);                        \
        }                                                                      \
    }                                                                          \
    _Pragma("unroll")                                                          \
    for (int m = 0; m < 4; m++) {                                              \
        MMA16816(pm[m][0], pm[m][1], pm[m][2], pm[m][3],                       \
                 afr[m][1][0], afr[m][1][1], afr[m][1][2], afr[m][1][3],       \
                 b0[1], b1[1]);                                                \
        MMA16816(qm[m][0], qm[m][1], qm[m][2], qm[m][3],                       \
                 afr[m][3][0], afr[m][3][1], afr[m][3][2], afr[m][3][3],       \
                 b0[3], b1[3]);                                                \
    }                                                                          \
    __half* hwrt = hbase + (pb ^ 1) * (8 * HP);                                \
    _Pragma("unroll")                                                          \
    for (int h = 0; h < 2; h++) {                                              \
        unsigned int ui = pkf(pm[2*h][0] + qm[2*h][0], pm[2*h][1] + qm[2*h][1]);     \
        unsigned int uf = pkf(pm[2*h][2] + qm[2*h][2], pm[2*h][3] + qm[2*h][3]);     \
        unsigned int ug = pkf(pm[2*h+1][0] + qm[2*h+1][0], pm[2*h+1][1] + qm[2*h+1][1]); \
        unsigned int uo = pkf(pm[2*h+1][2] + qm[2*h+1][2], pm[2*h+1][3] + qm[2*h+1][3]); \
        uint2 ca = xr[PH][h][0], cb_ = xr[PH][h][1];                           \
        unsigned int xi, xf, xg, xo;                                           \
        PRMT(xi, ca.x, cb_.x, 0x5410);                                         \
        PRMT(xf, ca.x, cb_.x, 0x7632);                                         \
        PRMT(xg, ca.y, cb_.y, 0x5410);                                         \
        PRMT(xo, ca.y, cb_.y, 0x7632);                                         \
        ui = hadd2u(ui, xi); uf = hadd2u(uf, xf);                              \
        ug = hadd2u(ug, xg); uo = hadd2u(uo, xo);                              \
        unsigned int hv = lstm_update(ui, uf, ug, uo, h ? cst1 : cst0);        \
        if (h) hn1 = hv; else hn0 = hv;                                        \
        if (real) {                                                            \
            __half2 hh = *(__half2*)&hv;                                       \
            int ec = h ? e1 : e0;                                              \
            hwrt[n0 * HP + ec]       = __low2half(hh);                         \
            hwrt[(n0 + 1) * HP + ec] = __high2half(hh);                        \
        }                                                                      \
    }                                                                          \
    GBAR();                                                                    \
    pb ^= 1;                                                                   \
    t += dt;                                                                   \
} while (0)

    for (int it = 0; it < 170; it++) {   // 510 steps
        LSTM_STEP(0);
        LSTM_STEP(1);
        LSTM_STEP(2);
    }
    LSTM_STEP(0);                        // step 510
    LSTM_STEP(1);                        // step 511

#undef LSTM_STEP
#undef GBAR

    if (real) {
        __half2 h0 = *(__half2*)&hn0;
        __half2 h1 = *(__half2*)&hn1;
        size_t base0 = (size_t)(dir * Bz + bg * 4 + n0) * Hz;
        size_t base1 = (size_t)(dir * Bz + bg * 4 + n0 + 1) * Hz;
        g_hfin[base0 + e0] = __low2float(h0);
        g_hfin[base1 + e0] = __high2float(h0);
        g_hfin[base0 + e1] = __low2float(h1);
        g_hfin[base1 + e1] = __high2float(h1);
    }
}

// ---------------------------------------------------------------------------
// Kernel 3: final FC + sigmoid
// ---------------------------------------------------------------------------
__global__ void final_fc(const float* __restrict__ fcw,
                         const float* __restrict__ fcb,
                         float* __restrict__ out)
{
    int b = threadIdx.x;
    if (b >= Bz) return;
    float acc = fcb[0];
    const float* hf = g_hfin + b * Hz;
    const float* hb = g_hfin + Bz * Hz + b * Hz;
#pragma unroll
    for (int u = 0; u < Hz; u++) {
        acc = fmaf(hf[u], fcw[u], acc);
        acc = fmaf(hb[u], fcw[Hz + u], acc);
    }
    out[b] = __fdividef(1.0f, 1.0f + __expf(-acc));
}

// ---------------------------------------------------------------------------
extern "C" void kernel_launch(void* const* d_in, const int* in_sizes, int n_in,
                              void* d_out, int out_size)
{
    const int*   x     = (const int*)  d_in[0];
    const float* emb   = (const float*)d_in[1];
    const float* Wih_f = (const float*)d_in[2];
    const float* Whh_f = (const float*)d_in[3];
    const float* bih_f = (const float*)d_in[4];
    const float* bhh_f = (const float*)d_in[5];
    const float* Wih_b = (const float*)d_in[6];
    const float* Whh_b = (const float*)d_in[7];
    const float* bih_b = (const float*)d_in[8];
    const float* bhh_b = (const float*)d_in[9];
    const float* fcw   = (const float*)d_in[10];
    const float* fcb   = (const float*)d_in[11];
    float* out = (float*)d_out;

    cvt_emb<<<VP / 4, 256>>>(emb);
    cvt_wih<<<512, 64>>>(Wih_f, Wih_b);

    dim3 g1(VP / 128, NC / 64);   // 391 x 8
    vocab_gemm<<<g1, 256>>>(bih_f, bhh_f, bih_b, bhh_b);

    lstm_rec<<<Bz / 4, 256>>>(x, Whh_f, Whh_b);   // 64 blocks, 2 groups each

    final_fc<<<1, 256>>>(fcw, fcb, out);
}